// round 12
// baseline (speedup 1.0000x reference)
#include <cuda_runtime.h>
#include <cuda_bf16.h>

// Problem constants (shapes fixed by setup_inputs; nhead=16 hardcoded)
#define B 16
#define S 4096
#define S1 4097
#define D 1024
#define H 16
#define SST 4104            // padded scores stride

typedef unsigned long long ull;

// ---------------- device scratch (no allocations allowed) ----------------
__device__ float d_qproj[B * D];
__device__ float d_qk[B * H * D];
__device__ float d_scores[B * H * SST];
__device__ float d_ctxraw[B * H * D];
__device__ float d_ctxproj[B * D];

// ---------------- helpers ----------------
__device__ __forceinline__ void fma2(ull& d, ull a, ull b) {
    asm("fma.rn.f32x2 %0, %1, %2, %0;" : "+l"(d) : "l"(a), "l"(b));
}
__device__ __forceinline__ ull dup2(float v) {
    ull r; unsigned u = __float_as_uint(v);
    asm("mov.b64 %0, {%1, %1};" : "=l"(r) : "r"(u));
    return r;
}
__device__ __forceinline__ float sum2(ull a) {
    float lo = __uint_as_float((unsigned)(a & 0xffffffffull));
    float hi = __uint_as_float((unsigned)(a >> 32));
    return lo + hi;
}
__device__ __forceinline__ float warp_red(float v) {
    #pragma unroll
    for (int o = 16; o > 0; o >>= 1) v += __shfl_xor_sync(0xffffffffu, v, o);
    return v;
}

// ---------------- 1. q projection: qproj = (query @ Wq^T + bq) * hd^-0.5 ----------------
__global__ void qproj_kernel(const float* __restrict__ query,
                             const float* __restrict__ w_in,
                             const float* __restrict__ b_in) {
    __shared__ float qs[D];
    int b = blockIdx.x, t = threadIdx.x;
    #pragma unroll
    for (int i = 0; i < 4; i++) qs[t + i * 256] = query[b * D + t + i * 256];
    __syncthreads();
    int w = t >> 5, l = t & 31;
    for (int r = w; r < D; r += 8) {
        const float* wr = w_in + (size_t)r * D;
        float acc = 0.f;
        #pragma unroll
        for (int p = 0; p < 8; p++) {
            float4 wv = *(const float4*)&wr[l * 4 + p * 128];
            float4 qv = *(const float4*)&qs[l * 4 + p * 128];
            acc += wv.x * qv.x + wv.y * qv.y + wv.z * qv.z + wv.w * qv.w;
        }
        acc = warp_red(acc);
        if (l == 0) d_qproj[b * D + r] = (acc + b_in[r]) * 0.125f;  // hd^-0.5 = 1/8
    }
}

// ---------------- 2. qk[b,h,j] = sum_dd qproj[b,h*64+dd] * Wk[h*64+dd, j] ----------------
__global__ void qk_kernel(const float* __restrict__ w_in) {
    int bh = blockIdx.x, b = bh >> 4, h = bh & 15, t = threadIdx.x;
    __shared__ float qs[64];
    if (t < 64) qs[t] = d_qproj[b * D + h * 64 + t];
    __syncthreads();
    const float* wk = w_in + (size_t)(D + h * 64) * D;
    #pragma unroll
    for (int i = 0; i < 4; i++) {
        int j = t + i * 256;
        float acc = 0.f;
        #pragma unroll 8
        for (int dd = 0; dd < 64; dd++) acc += qs[dd] * wk[(size_t)dd * D + j];
        d_qk[(b * H + h) * D + j] = acc;
    }
}

// ---------------- 3. pass1: copy past_key->comb_key + scores = comb_key @ qk^T ----------------
// block: 256 rows of one batch; 8 warps, each warp a 32s x 16h tile.
// 16 j-chunks of 64 cols. smem: qk_s[16][68] (restaged per chunk) + comb_s[256][68]
// 74 KB smem -> occupancy 2, staging of one CTA overlaps compute of the other.
#define CBS2 68
__global__ __launch_bounds__(256, 2)
void pass1_kernel(const float* __restrict__ past_key,
                  const float* __restrict__ key,
                  float* __restrict__ ck_out) {
    extern __shared__ float sm[];
    float* qk_s = sm;                   // 16*68 floats
    float* comb_s = sm + 16 * CBS2;     // 256*68 floats

    int t = threadIdx.x;
    int b = blockIdx.y;
    int s0 = blockIdx.x * 256;
    int nrows = S1 - s0; if (nrows > 256) nrows = 256;

    const float* qkg = d_qk + b * H * D;

    int w = t >> 5, l = t & 31;
    int lc = l & 3, lr = l >> 2;       // lc: head quarter, lr: row octet

    ull acc[4][4];
    #pragma unroll
    for (int k = 0; k < 4; k++)
        #pragma unroll
        for (int m = 0; m < 4; m++) acc[k][m] = 0ull;

    for (int c = 0; c < 16; c++) {     // j-chunks of 64
        __syncthreads();
        // stage qk chunk: 16 heads x 64 floats (one float4 per thread)
        {
            int h = t >> 4, c4 = t & 15;
            *(float4*)&qk_s[h * CBS2 + c4 * 4] =
                *(const float4*)&qkg[h * D + c * 64 + c4 * 4];
        }
        // stage 256 rows x 64 floats ; also write comb_key output
        #pragma unroll 4
        for (int i = 0; i < 16; i++) {
            int idx = t + i * 256;
            int row = idx >> 4, c4 = idx & 15;
            float4 v;
            if (row < nrows) {
                int s = s0 + row;
                if (s < S) v = *(const float4*)&past_key[((size_t)b * S + s) * D + c * 64 + c4 * 4];
                else       v = *(const float4*)&key[b * D + c * 64 + c4 * 4];
                *(float4*)&ck_out[((size_t)b * S1 + s) * D + c * 64 + c4 * 4] = v;
            } else {
                v = make_float4(0.f, 0.f, 0.f, 0.f);
            }
            *(float4*)&comb_s[row * CBS2 + c4 * 4] = v;
        }
        __syncthreads();
        #pragma unroll 2
        for (int jp = 0; jp < 32; jp++) {
            ull c2[4], q2[4];
            #pragma unroll
            for (int k = 0; k < 4; k++)
                c2[k] = *(const ull*)&comb_s[(w * 32 + k * 8 + lr) * CBS2 + jp * 2];
            #pragma unroll
            for (int m = 0; m < 4; m++)
                q2[m] = *(const ull*)&qk_s[(m * 4 + lc) * CBS2 + jp * 2];
            #pragma unroll
            for (int k = 0; k < 4; k++)
                #pragma unroll
                for (int m = 0; m < 4; m++) fma2(acc[k][m], c2[k], q2[m]);
        }
    }
    // store scores
    #pragma unroll
    for (int k = 0; k < 4; k++) {
        int rr = w * 32 + k * 8 + lr;
        if (rr < nrows) {
            int s = s0 + rr;
            #pragma unroll
            for (int m = 0; m < 4; m++) {
                int h = m * 4 + lc;
                d_scores[(b * H + h) * SST + s] = sum2(acc[k][m]);
            }
        }
    }
}

// ---------------- 4. softmax over s per (b,h), in-place; also zero ctxraw ----------------
__global__ void softmax_kernel() {
    __shared__ float red[256];
    int bh = blockIdx.x, t = threadIdx.x;
    float* sc = d_scores + bh * SST;

    float m = -1e30f;
    for (int i = t; i < S1; i += 256) m = fmaxf(m, sc[i]);
    red[t] = m; __syncthreads();
    #pragma unroll
    for (int o = 128; o > 0; o >>= 1) { if (t < o) red[t] = fmaxf(red[t], red[t + o]); __syncthreads(); }
    float M = red[0]; __syncthreads();

    float sum = 0.f;
    for (int i = t; i < S1; i += 256) { float e = __expf(sc[i] - M); sc[i] = e; sum += e; }
    red[t] = sum; __syncthreads();
    #pragma unroll
    for (int o = 128; o > 0; o >>= 1) { if (t < o) red[t] += red[t + o]; __syncthreads(); }
    float inv = 1.0f / red[0];

    for (int i = t; i < S1; i += 256) sc[i] *= inv;
    for (int i = t; i < D; i += 256) d_ctxraw[bh * D + i] = 0.f;
}

// ---------------- 5. pass2: copy past_value->comb_value + ctxraw += attn @ comb_value ----------------
// block: 256 rows, 8 s-chunks of 32 rows, 2 j-halves of 512.
// smem: v_s[32][520] + attn_s[16][33] (ull)  = 70.8 KB -> occupancy 2.
#define VST 520
__global__ __launch_bounds__(256, 2)
void pass2_kernel(const float* __restrict__ past_value,
                  const float* __restrict__ value,
                  float* __restrict__ cv_out) {
    extern __shared__ float sm[];
    float* v_s = sm;                             // 32*520 floats
    ull* attn_s = (ull*)(sm + 32 * VST);         // 16*33 ull

    int t = threadIdx.x;
    int b = blockIdx.y;
    int s0 = blockIdx.x * 256;
    int nrows = S1 - s0; if (nrows > 256) nrows = 256;

    int w = t >> 5, l = t & 31;
    int lh = l >> 3, lj = l & 7;
    int jbase = w * 64;

    for (int jh = 0; jh < 2; jh++) {
        ull acc[4][4];
        #pragma unroll
        for (int a = 0; a < 4; a++)
            #pragma unroll
            for (int m = 0; m < 4; m++) acc[a][m] = 0ull;

        for (int scn = 0; scn < 8; scn++) {
            __syncthreads();
            // stage v: 32 rows x 512 floats (+ write comb_value)
            #pragma unroll 4
            for (int i = 0; i < 16; i++) {
                int idx = t + i * 256;
                int row = idx >> 7, c4 = idx & 127;
                int rr = scn * 32 + row;
                float4 v;
                if (rr < nrows) {
                    int s = s0 + rr;
                    if (s < S) v = *(const float4*)&past_value[((size_t)b * S + s) * D + jh * 512 + c4 * 4];
                    else       v = *(const float4*)&value[b * D + jh * 512 + c4 * 4];
                    *(float4*)&cv_out[((size_t)b * S1 + s) * D + jh * 512 + c4 * 4] = v;
                } else {
                    v = make_float4(0.f, 0.f, 0.f, 0.f);
                }
                *(float4*)&v_s[row * VST + c4 * 4] = v;
            }
            // stage attn (duplicated pairs): 16h x 32s
            #pragma unroll
            for (int i = 0; i < 2; i++) {
                int idx = t + i * 256;
                int h = idx >> 5, ss = idx & 31;
                int rr = scn * 32 + ss;
                float a = (rr < nrows) ? d_scores[(b * H + h) * SST + s0 + rr] : 0.f;
                attn_s[h * 33 + ss] = dup2(a);
            }
            __syncthreads();
            #pragma unroll 2
            for (int s = 0; s < 32; s++) {
                ull a2[4], v2[4];
                #pragma unroll
                for (int hh = 0; hh < 4; hh++) a2[hh] = attn_s[(lh * 4 + hh) * 33 + s];
                #pragma unroll
                for (int m = 0; m < 4; m++)
                    v2[m] = *(const ull*)&v_s[s * VST + jbase + (lj + 8 * m) * 2];
                #pragma unroll
                for (int hh = 0; hh < 4; hh++)
                    #pragma unroll
                    for (int m = 0; m < 4; m++) fma2(acc[hh][m], a2[hh], v2[m]);
            }
        }
        // accumulate partial ctx into global
        float* cr = d_ctxraw + b * H * D;
        #pragma unroll
        for (int hh = 0; hh < 4; hh++) {
            int h = lh * 4 + hh;
            #pragma unroll
            for (int m = 0; m < 4; m++) {
                int j = jh * 512 + jbase + (lj + 8 * m) * 2;
                float lo = __uint_as_float((unsigned)(acc[hh][m] & 0xffffffffull));
                float hi = __uint_as_float((unsigned)(acc[hh][m] >> 32));
                atomicAdd(&cr[h * D + j], lo);
                atomicAdd(&cr[h * D + j + 1], hi);
            }
        }
    }
}

// ---------------- 6. ctxproj[b, h*64+dd] = ctxraw[b,h,:] . Wv[h*64+dd,:] + bv ----------------
__global__ void ctxproj_kernel(const float* __restrict__ w_in,
                               const float* __restrict__ b_in) {
    __shared__ float cs[D];
    int bh = blockIdx.x, b = bh >> 4, h = bh & 15, t = threadIdx.x;
    #pragma unroll
    for (int i = 0; i < 4; i++) cs[t + i * 256] = d_ctxraw[bh * D + t + i * 256];
    __syncthreads();
    int w = t >> 5, l = t & 31;
    #pragma unroll 1
    for (int it = 0; it < 8; it++) {
        int dd = it * 8 + w;
        int row = h * 64 + dd;
        const float* wr = w_in + (size_t)(2 * D + row) * D;
        float acc = 0.f;
        #pragma unroll
        for (int p = 0; p < 8; p++) {
            float4 wv = *(const float4*)&wr[l * 4 + p * 128];
            float4 cv = *(const float4*)&cs[l * 4 + p * 128];
            acc += wv.x * cv.x + wv.y * cv.y + wv.z * cv.z + wv.w * cv.w;
        }
        acc = warp_red(acc);
        if (l == 0) d_ctxproj[b * D + row] = acc + b_in[2 * D + row];
    }
}

// ---------------- 7. out[b,e] = ctxproj[b,:] . Wout[e,:] + bout ----------------
__global__ void out_kernel(const float* __restrict__ w_out,
                           const float* __restrict__ b_out,
                           float* __restrict__ out) {
    __shared__ float cp[D];
    int eg = blockIdx.x, b = blockIdx.y, t = threadIdx.x;
    #pragma unroll
    for (int i = 0; i < 4; i++) cp[t + i * 256] = d_ctxproj[b * D + t + i * 256];
    __syncthreads();
    int w = t >> 5, l = t & 31;
    #pragma unroll 1
    for (int it = 0; it < 16; it++) {
        int e = eg * 128 + it * 8 + w;
        const float* wr = w_out + (size_t)e * D;
        float acc = 0.f;
        #pragma unroll
        for (int p = 0; p < 8; p++) {
            float4 wv = *(const float4*)&wr[l * 4 + p * 128];
            float4 cv = *(const float4*)&cp[l * 4 + p * 128];
            acc += wv.x * cv.x + wv.y * cv.y + wv.z * cv.z + wv.w * cv.w;
        }
        acc = warp_red(acc);
        if (l == 0) out[b * D + e] = acc + b_out[e];
    }
}

// ---------------- launch ----------------
extern "C" void kernel_launch(void* const* d_in, const int* in_sizes, int n_in,
                              void* d_out, int out_size) {
    const float* query      = (const float*)d_in[0];
    const float* key        = (const float*)d_in[1];
    const float* value      = (const float*)d_in[2];
    const float* past_key   = (const float*)d_in[3];
    const float* past_value = (const float*)d_in[4];
    const float* w_in       = (const float*)d_in[5];
    const float* b_in       = (const float*)d_in[6];
    const float* w_out      = (const float*)d_in[7];
    const float* b_out      = (const float*)d_in[8];
    // d_in[9] = nhead (=16, hardcoded)

    float* out = (float*)d_out;
    float* ck  = out + (size_t)B * D;                    // comb_key
    float* cv  = ck + (size_t)B * S1 * D;                // comb_value

    int smem1 = (16 * CBS2 + 256 * CBS2) * sizeof(float);          // 73,984 B -> occ 2
    int smem2 = 32 * VST * sizeof(float) + 16 * 33 * sizeof(ull);  // 70,784 B -> occ 2
    cudaFuncSetAttribute(pass1_kernel, cudaFuncAttributeMaxDynamicSharedMemorySize, smem1);
    cudaFuncSetAttribute(pass2_kernel, cudaFuncAttributeMaxDynamicSharedMemorySize, smem2);

    qproj_kernel<<<B, 256>>>(query, w_in, b_in);
    qk_kernel<<<B * H, 256>>>(w_in);
    pass1_kernel<<<dim3(17, B), 256, smem1>>>(past_key, key, ck);
    softmax_kernel<<<B * H, 256>>>();
    pass2_kernel<<<dim3(17, B), 256, smem2>>>(past_value, value, cv);
    ctxproj_kernel<<<B * H, 256>>>(w_in, b_in);
    out_kernel<<<dim3(8, B), 256>>>(w_out, b_out, out);
}

// round 13
// speedup vs baseline: 1.2289x; 1.2289x over previous
#include <cuda_runtime.h>
#include <cuda_bf16.h>

// Shapes fixed by setup_inputs; nhead=16 hardcoded
#define B 16
#define S 4096
#define S1 4097
#define D 1024
#define H 16
#define SST 4104

typedef unsigned long long ull;

// ---------------- device scratch ----------------
__device__ float d_qproj[B * D];
__device__ float d_qk[B * H * D];
__device__ float d_scores[B * H * SST];
__device__ float d_ctxraw[B * H * D];
__device__ float d_ctxproj[B * D];

// ---------------- helpers ----------------
__device__ __forceinline__ void fma2(ull& d, ull a, ull b) {
    asm("fma.rn.f32x2 %0, %1, %2, %0;" : "+l"(d) : "l"(a), "l"(b));
}
__device__ __forceinline__ ull dup2(float v) {
    ull r; unsigned u = __float_as_uint(v);
    asm("mov.b64 %0, {%1, %1};" : "=l"(r) : "r"(u));
    return r;
}
__device__ __forceinline__ float sum2(ull a) {
    float lo = __uint_as_float((unsigned)(a & 0xffffffffull));
    float hi = __uint_as_float((unsigned)(a >> 32));
    return lo + hi;
}
__device__ __forceinline__ float warp_red(float v) {
    #pragma unroll
    for (int o = 16; o > 0; o >>= 1) v += __shfl_xor_sync(0xffffffffu, v, o);
    return v;
}
__device__ __forceinline__ float warp_max(float v) {
    #pragma unroll
    for (int o = 16; o > 0; o >>= 1) v = fmaxf(v, __shfl_xor_sync(0xffffffffu, v, o));
    return v;
}

// ---------------- 1. qproj = (query @ Wq^T + bq) / 8 ----------------
__global__ void qproj_kernel(const float* __restrict__ query,
                             const float* __restrict__ w_in,
                             const float* __restrict__ b_in) {
    __shared__ float qs[D];
    int b = blockIdx.x, t = threadIdx.x;
    #pragma unroll
    for (int i = 0; i < 4; i++) qs[t + i * 256] = query[b * D + t + i * 256];
    __syncthreads();
    int w = t >> 5, l = t & 31;
    for (int r = w; r < D; r += 8) {
        const float* wr = w_in + (size_t)r * D;
        float acc = 0.f;
        #pragma unroll
        for (int p = 0; p < 8; p++) {
            float4 wv = *(const float4*)&wr[l * 4 + p * 128];
            float4 qv = *(const float4*)&qs[l * 4 + p * 128];
            acc += wv.x * qv.x + wv.y * qv.y + wv.z * qv.z + wv.w * qv.w;
        }
        acc = warp_red(acc);
        if (l == 0) d_qproj[b * D + r] = (acc + b_in[r]) * 0.125f;
    }
}

// ---------------- 2. qk[b,h,j] = sum_dd qproj[b,h*64+dd]*Wk[h*64+dd,j]; zero ctxraw ----------------
__global__ void qk_kernel(const float* __restrict__ w_in) {
    int bh = blockIdx.x, b = bh >> 4, h = bh & 15, t = threadIdx.x;
    __shared__ float qs[64];
    if (t < 64) qs[t] = d_qproj[b * D + h * 64 + t];
    __syncthreads();
    const float* wk = w_in + (size_t)(D + h * 64) * D;
    #pragma unroll
    for (int i = 0; i < 4; i++) {
        int j = t + i * 256;
        float acc = 0.f;
        #pragma unroll 8
        for (int dd = 0; dd < 64; dd++) acc += qs[dd] * wk[(size_t)dd * D + j];
        d_qk[(b * H + h) * D + j] = acc;
        d_ctxraw[(b * H + h) * D + j] = 0.f;
    }
}

// ---------------- 3. pass1: KV-copy + raw scores, persistent + double-buffered ----------------
#define ITEMS 272
#define GRID1 148
#define CBS2 68
#define BUF1 (16 * CBS2 + 256 * CBS2)   // floats per buffer

__global__ __launch_bounds__(256, 1)
void pass1_kernel(const float* __restrict__ past_key,
                  const float* __restrict__ key,
                  float* __restrict__ ck_out) {
    extern __shared__ float sm[];
    int t = threadIdx.x;
    int w = t >> 5, l = t & 31;
    int lc = l & 3, lr = l >> 2;
    int hq = t >> 4, hc4 = t & 15;   // qk staging role

    for (int item = blockIdx.x; item < ITEMS; item += GRID1) {
        int b = item & 15;
        int s0 = (item >> 4) * 256;
        int nrows = S1 - s0; if (nrows > 256) nrows = 256;
        const float* qkg = d_qk + b * H * D;

        float4 r[16]; float4 rq;
        // prefetch chunk 0
        #pragma unroll
        for (int i = 0; i < 16; i++) {
            int idx = t + i * 256, row = idx >> 4, c4 = idx & 15;
            if (row < nrows) {
                int s = s0 + row;
                r[i] = (s < S) ? *(const float4*)&past_key[((size_t)b * S + s) * D + c4 * 4]
                               : *(const float4*)&key[b * D + c4 * 4];
            } else r[i] = make_float4(0.f, 0.f, 0.f, 0.f);
        }
        rq = *(const float4*)&qkg[hq * D + hc4 * 4];
        {
            float* qs = sm;
            float* cs = sm + 16 * CBS2;
            #pragma unroll
            for (int i = 0; i < 16; i++) {
                int idx = t + i * 256, row = idx >> 4, c4 = idx & 15;
                if (row < nrows)
                    *(float4*)&ck_out[((size_t)b * S1 + s0 + row) * D + c4 * 4] = r[i];
                *(float4*)&cs[row * CBS2 + c4 * 4] = r[i];
            }
            *(float4*)&qs[hq * CBS2 + hc4 * 4] = rq;
        }
        __syncthreads();

        ull acc[4][4];
        #pragma unroll
        for (int k = 0; k < 4; k++)
            #pragma unroll
            for (int m = 0; m < 4; m++) acc[k][m] = 0ull;

        for (int c = 0; c < 16; c++) {
            // issue loads for chunk c+1 (overlap with compute below)
            if (c < 15) {
                #pragma unroll
                for (int i = 0; i < 16; i++) {
                    int idx = t + i * 256, row = idx >> 4, c4 = idx & 15;
                    if (row < nrows) {
                        int s = s0 + row;
                        r[i] = (s < S) ? *(const float4*)&past_key[((size_t)b * S + s) * D + (c + 1) * 64 + c4 * 4]
                                       : *(const float4*)&key[b * D + (c + 1) * 64 + c4 * 4];
                    } else r[i] = make_float4(0.f, 0.f, 0.f, 0.f);
                }
                rq = *(const float4*)&qkg[hq * D + (c + 1) * 64 + hc4 * 4];
            }
            // compute chunk c
            {
                const float* qs = sm + (c & 1) * BUF1;
                const float* cs = qs + 16 * CBS2;
                #pragma unroll 2
                for (int jp = 0; jp < 32; jp++) {
                    ull c2[4], q2[4];
                    #pragma unroll
                    for (int k = 0; k < 4; k++)
                        c2[k] = *(const ull*)&cs[(w * 32 + k * 8 + lr) * CBS2 + jp * 2];
                    #pragma unroll
                    for (int m = 0; m < 4; m++)
                        q2[m] = *(const ull*)&qs[(m * 4 + lc) * CBS2 + jp * 2];
                    #pragma unroll
                    for (int k = 0; k < 4; k++)
                        #pragma unroll
                        for (int m = 0; m < 4; m++) fma2(acc[k][m], c2[k], q2[m]);
                }
            }
            // drain chunk c+1 into global + other smem buffer
            if (c < 15) {
                float* qs = sm + ((c + 1) & 1) * BUF1;
                float* cs = qs + 16 * CBS2;
                #pragma unroll
                for (int i = 0; i < 16; i++) {
                    int idx = t + i * 256, row = idx >> 4, c4 = idx & 15;
                    if (row < nrows)
                        *(float4*)&ck_out[((size_t)b * S1 + s0 + row) * D + (c + 1) * 64 + c4 * 4] = r[i];
                    *(float4*)&cs[row * CBS2 + c4 * 4] = r[i];
                }
                *(float4*)&qs[hq * CBS2 + hc4 * 4] = rq;
            }
            __syncthreads();
        }
        // store raw scores
        #pragma unroll
        for (int k = 0; k < 4; k++) {
            int rr = w * 32 + k * 8 + lr;
            if (rr < nrows) {
                int s = s0 + rr;
                #pragma unroll
                for (int m = 0; m < 4; m++)
                    d_scores[(b * H + m * 4 + lc) * SST + s] = sum2(acc[k][m]);
            }
        }
    }
}

// ---------------- 4. pass2: V-copy + fused softmax + ctx accumulation ----------------
#define VST 520
#define BUF2V (32 * VST)              // floats
#define ATT_F (16 * 33 * 2)           // attn ull region in float units
#define BUF2 (BUF2V + ATT_F)          // floats per buffer

__global__ __launch_bounds__(256, 1)
void pass2_kernel(const float* __restrict__ past_value,
                  const float* __restrict__ value,
                  float* __restrict__ cv_out) {
    extern __shared__ float sm[];
    float* Msm = sm + 2 * BUF2;
    float* ISsm = Msm + 16;
    int t = threadIdx.x;
    int w = t >> 5, l = t & 31;
    int lh = l >> 3, lj = l & 7;
    int jbase = w * 64;

    for (int item = blockIdx.x; item < ITEMS; item += GRID1) {
        int b = item & 15;
        int s0 = (item >> 4) * 256;
        int nrows = S1 - s0; if (nrows > 256) nrows = 256;

        // softmax stats per head (warp w handles heads 2w, 2w+1)
        {
            const float* scb = d_scores + b * H * SST;
            #pragma unroll
            for (int hh = 0; hh < 2; hh++) {
                int h = w * 2 + hh;
                const float* sc = scb + h * SST;
                float mx = -1e30f;
                for (int i = l; i < S1; i += 32) mx = fmaxf(mx, sc[i]);
                mx = warp_max(mx);
                float sum = 0.f;
                for (int i = l; i < S1; i += 32) sum += __expf(sc[i] - mx);
                sum = warp_red(sum);
                if (l == 0) { Msm[h] = mx; ISsm[h] = 1.0f / sum; }
            }
        }
        __syncthreads();
        const float* scb = d_scores + b * H * SST;

        float4 r[16]; float ra0, ra1;
        // prefetch chunk 0 (jh=0, scn=0)
        #pragma unroll
        for (int i = 0; i < 16; i++) {
            int idx = t + i * 256, row = idx >> 7, c4 = idx & 127;
            if (row < nrows) {
                int s = s0 + row;
                r[i] = (s < S) ? *(const float4*)&past_value[((size_t)b * S + s) * D + c4 * 4]
                               : *(const float4*)&value[b * D + c4 * 4];
            } else r[i] = make_float4(0.f, 0.f, 0.f, 0.f);
        }
        {
            int h0 = t >> 5, ss0 = t & 31;
            ra0 = (ss0 < nrows) ? __expf(scb[h0 * SST + s0 + ss0] - Msm[h0]) * ISsm[h0] : 0.f;
            int idx1 = t + 256; int h1 = idx1 >> 5, ss1 = idx1 & 31;
            ra1 = (ss1 < nrows) ? __expf(scb[h1 * SST + s0 + ss1] - Msm[h1]) * ISsm[h1] : 0.f;
        }
        {
            float* vs = sm;
            ull* as = (ull*)(sm + BUF2V);
            #pragma unroll
            for (int i = 0; i < 16; i++) {
                int idx = t + i * 256, row = idx >> 7, c4 = idx & 127;
                if (row < nrows)
                    *(float4*)&cv_out[((size_t)b * S1 + s0 + row) * D + c4 * 4] = r[i];
                *(float4*)&vs[row * VST + c4 * 4] = r[i];
            }
            as[(t >> 5) * 33 + (t & 31)] = dup2(ra0);
            as[((t + 256) >> 5) * 33 + (t & 31)] = dup2(ra1);
        }
        __syncthreads();

        ull acc[4][4];
        #pragma unroll
        for (int a = 0; a < 4; a++)
            #pragma unroll
            for (int m = 0; m < 4; m++) acc[a][m] = 0ull;

        for (int c = 0; c < 16; c++) {
            int jh1 = (c + 1) >> 3, scn1 = (c + 1) & 7;
            if (c < 15) {
                #pragma unroll
                for (int i = 0; i < 16; i++) {
                    int idx = t + i * 256, row = idx >> 7, c4 = idx & 127;
                    int rr = scn1 * 32 + row;
                    if (rr < nrows) {
                        int s = s0 + rr;
                        r[i] = (s < S) ? *(const float4*)&past_value[((size_t)b * S + s) * D + jh1 * 512 + c4 * 4]
                                       : *(const float4*)&value[b * D + jh1 * 512 + c4 * 4];
                    } else r[i] = make_float4(0.f, 0.f, 0.f, 0.f);
                }
                {
                    int h0 = t >> 5, ss0 = t & 31;
                    int rr0 = scn1 * 32 + ss0;
                    ra0 = (rr0 < nrows) ? __expf(scb[h0 * SST + s0 + rr0] - Msm[h0]) * ISsm[h0] : 0.f;
                    int idx1 = t + 256; int h1 = idx1 >> 5, ss1 = idx1 & 31;
                    int rr1 = scn1 * 32 + ss1;
                    ra1 = (rr1 < nrows) ? __expf(scb[h1 * SST + s0 + rr1] - Msm[h1]) * ISsm[h1] : 0.f;
                }
            }
            // compute chunk c
            {
                const float* vs = sm + (c & 1) * BUF2;
                const ull* as = (const ull*)(vs + BUF2V);
                #pragma unroll 2
                for (int s = 0; s < 32; s++) {
                    ull a2[4], v2[4];
                    #pragma unroll
                    for (int hh = 0; hh < 4; hh++) a2[hh] = as[(lh * 4 + hh) * 33 + s];
                    #pragma unroll
                    for (int m = 0; m < 4; m++)
                        v2[m] = *(const ull*)&vs[s * VST + jbase + (lj + 8 * m) * 2];
                    #pragma unroll
                    for (int hh = 0; hh < 4; hh++)
                        #pragma unroll
                        for (int m = 0; m < 4; m++) fma2(acc[hh][m], a2[hh], v2[m]);
                }
            }
            // dump accumulators at the end of each j-half
            if (c == 7 || c == 15) {
                int jh = c >> 3;
                float* cr = d_ctxraw + b * H * D;
                #pragma unroll
                for (int hh = 0; hh < 4; hh++) {
                    int h = lh * 4 + hh;
                    #pragma unroll
                    for (int m = 0; m < 4; m++) {
                        int j = jh * 512 + jbase + (lj + 8 * m) * 2;
                        atomicAdd(&cr[h * D + j],
                                  __uint_as_float((unsigned)(acc[hh][m] & 0xffffffffull)));
                        atomicAdd(&cr[h * D + j + 1],
                                  __uint_as_float((unsigned)(acc[hh][m] >> 32)));
                        acc[hh][m] = 0ull;
                    }
                }
            }
            // drain chunk c+1
            if (c < 15) {
                float* vs = sm + ((c + 1) & 1) * BUF2;
                ull* as = (ull*)(vs + BUF2V);
                #pragma unroll
                for (int i = 0; i < 16; i++) {
                    int idx = t + i * 256, row = idx >> 7, c4 = idx & 127;
                    int rr = scn1 * 32 + row;
                    if (rr < nrows)
                        *(float4*)&cv_out[((size_t)b * S1 + s0 + rr) * D + jh1 * 512 + c4 * 4] = r[i];
                    *(float4*)&vs[row * VST + c4 * 4] = r[i];
                }
                as[(t >> 5) * 33 + (t & 31)] = dup2(ra0);
                as[((t + 256) >> 5) * 33 + (t & 31)] = dup2(ra1);
            }
            __syncthreads();
        }
    }
}

// ---------------- 5. ctxproj = ctxraw . Wv + bv ----------------
__global__ void ctxproj_kernel(const float* __restrict__ w_in,
                               const float* __restrict__ b_in) {
    __shared__ float cs[D];
    int bh = blockIdx.x, b = bh >> 4, h = bh & 15, t = threadIdx.x;
    #pragma unroll
    for (int i = 0; i < 4; i++) cs[t + i * 256] = d_ctxraw[bh * D + t + i * 256];
    __syncthreads();
    int w = t >> 5, l = t & 31;
    #pragma unroll 1
    for (int it = 0; it < 8; it++) {
        int row = h * 64 + it * 8 + w;
        const float* wr = w_in + (size_t)(2 * D + row) * D;
        float acc = 0.f;
        #pragma unroll
        for (int p = 0; p < 8; p++) {
            float4 wv = *(const float4*)&wr[l * 4 + p * 128];
            float4 cv = *(const float4*)&cs[l * 4 + p * 128];
            acc += wv.x * cv.x + wv.y * cv.y + wv.z * cv.z + wv.w * cv.w;
        }
        acc = warp_red(acc);
        if (l == 0) d_ctxproj[b * D + row] = acc + b_in[2 * D + row];
    }
}

// ---------------- 6. out = ctxproj . Wout^T + bout ----------------
__global__ void out_kernel(const float* __restrict__ w_out,
                           const float* __restrict__ b_out,
                           float* __restrict__ out) {
    __shared__ float cp[D];
    int eg = blockIdx.x, b = blockIdx.y, t = threadIdx.x;
    #pragma unroll
    for (int i = 0; i < 4; i++) cp[t + i * 256] = d_ctxproj[b * D + t + i * 256];
    __syncthreads();
    int w = t >> 5, l = t & 31;
    #pragma unroll 1
    for (int it = 0; it < 16; it++) {
        int e = eg * 128 + it * 8 + w;
        const float* wr = w_out + (size_t)e * D;
        float acc = 0.f;
        #pragma unroll
        for (int p = 0; p < 8; p++) {
            float4 wv = *(const float4*)&wr[l * 4 + p * 128];
            float4 cv = *(const float4*)&cp[l * 4 + p * 128];
            acc += wv.x * cv.x + wv.y * cv.y + wv.z * cv.z + wv.w * cv.w;
        }
        acc = warp_red(acc);
        if (l == 0) out[b * D + e] = acc + b_out[e];
    }
}

// ---------------- launch ----------------
extern "C" void kernel_launch(void* const* d_in, const int* in_sizes, int n_in,
                              void* d_out, int out_size) {
    const float* query      = (const float*)d_in[0];
    const float* key        = (const float*)d_in[1];
    const float* value      = (const float*)d_in[2];
    const float* past_key   = (const float*)d_in[3];
    const float* past_value = (const float*)d_in[4];
    const float* w_in       = (const float*)d_in[5];
    const float* b_in       = (const float*)d_in[6];
    const float* w_out      = (const float*)d_in[7];
    const float* b_out      = (const float*)d_in[8];

    float* out = (float*)d_out;
    float* ck  = out + (size_t)B * D;
    float* cv  = ck + (size_t)B * S1 * D;

    int smem1 = 2 * BUF1 * sizeof(float);               // 147,968 B
    int smem2 = (2 * BUF2 + 32) * sizeof(float);        // 141,696 B
    cudaFuncSetAttribute(pass1_kernel, cudaFuncAttributeMaxDynamicSharedMemorySize, smem1);
    cudaFuncSetAttribute(pass2_kernel, cudaFuncAttributeMaxDynamicSharedMemorySize, smem2);

    qproj_kernel<<<B, 256>>>(query, w_in, b_in);
    qk_kernel<<<B * H, 256>>>(w_in);
    pass1_kernel<<<GRID1, 256, smem1>>>(past_key, key, ck);
    pass2_kernel<<<GRID1, 256, smem2>>>(past_value, value, cv);
    ctxproj_kernel<<<B * H, 256>>>(w_in, b_in);
    out_kernel<<<dim3(8, B), 256>>>(w_out, b_out, out);
}

// round 14
// speedup vs baseline: 1.3885x; 1.1298x over previous
#include <cuda_runtime.h>
#include <cuda_bf16.h>

// Shapes fixed by setup_inputs; nhead=16 hardcoded
#define B 16
#define S 4096
#define S1 4097
#define D 1024
#define H 16
#define SST 4104

typedef unsigned long long ull;

// ---------------- device scratch ----------------
__device__ float d_qproj[B * D];
__device__ float d_qk[B * H * D];
__device__ float d_scores[B * H * SST];
__device__ float d_ctxraw[B * H * D];
__device__ float d_ctxproj[B * D];

// ---------------- helpers ----------------
__device__ __forceinline__ void fma2(ull& d, ull a, ull b) {
    asm("fma.rn.f32x2 %0, %1, %2, %0;" : "+l"(d) : "l"(a), "l"(b));
}
__device__ __forceinline__ ull dup2(float v) {
    ull r; unsigned u = __float_as_uint(v);
    asm("mov.b64 %0, {%1, %1};" : "=l"(r) : "r"(u));
    return r;
}
__device__ __forceinline__ float sum2(ull a) {
    float lo = __uint_as_float((unsigned)(a & 0xffffffffull));
    float hi = __uint_as_float((unsigned)(a >> 32));
    return lo + hi;
}
__device__ __forceinline__ float warp_red(float v) {
    #pragma unroll
    for (int o = 16; o > 0; o >>= 1) v += __shfl_xor_sync(0xffffffffu, v, o);
    return v;
}
__device__ __forceinline__ float warp_max(float v) {
    #pragma unroll
    for (int o = 16; o > 0; o >>= 1) v = fmaxf(v, __shfl_xor_sync(0xffffffffu, v, o));
    return v;
}

// ---------------- 1. qproj = (query @ Wq^T + bq) / 8 ----------------
__global__ void qproj_kernel(const float* __restrict__ query,
                             const float* __restrict__ w_in,
                             const float* __restrict__ b_in) {
    __shared__ float qs[D];
    int b = blockIdx.x, t = threadIdx.x;
    #pragma unroll
    for (int i = 0; i < 4; i++) qs[t + i * 256] = query[b * D + t + i * 256];
    __syncthreads();
    int w = t >> 5, l = t & 31;
    for (int r = w; r < D; r += 8) {
        const float* wr = w_in + (size_t)r * D;
        float acc = 0.f;
        #pragma unroll
        for (int p = 0; p < 8; p++) {
            float4 wv = *(const float4*)&wr[l * 4 + p * 128];
            float4 qv = *(const float4*)&qs[l * 4 + p * 128];
            acc += wv.x * qv.x + wv.y * qv.y + wv.z * qv.z + wv.w * qv.w;
        }
        acc = warp_red(acc);
        if (l == 0) d_qproj[b * D + r] = (acc + b_in[r]) * 0.125f;
    }
}

// ---------------- 2. qk + zero ctxraw ----------------
__global__ void qk_kernel(const float* __restrict__ w_in) {
    int bh = blockIdx.x, b = bh >> 4, h = bh & 15, t = threadIdx.x;
    __shared__ float qs[64];
    if (t < 64) qs[t] = d_qproj[b * D + h * 64 + t];
    __syncthreads();
    const float* wk = w_in + (size_t)(D + h * 64) * D;
    #pragma unroll
    for (int i = 0; i < 4; i++) {
        int j = t + i * 256;
        float acc = 0.f;
        #pragma unroll 8
        for (int dd = 0; dd < 64; dd++) acc += qs[dd] * wk[(size_t)dd * D + j];
        d_qk[(b * H + h) * D + j] = acc;
        d_ctxraw[(b * H + h) * D + j] = 0.f;
    }
}

// ---------------- 3. pass1: KV-copy + raw scores (512 thr, persistent, dbl-buffered) ----------------
#define ITEMS 272
#define GRID1 148
#define CBS2 68
#define BUF1 (16 * CBS2 + 256 * CBS2)

__global__ __launch_bounds__(512, 1)
void pass1_kernel(const float* __restrict__ past_key,
                  const float* __restrict__ key,
                  float* __restrict__ ck_out) {
    extern __shared__ float sm[];
    int t = threadIdx.x;
    int w = t >> 5, l = t & 31;
    int lc = l & 3, lr = l >> 2;
    int hq = t >> 4, hc4 = t & 15;      // qk staging role (t < 256 only)

    for (int item = blockIdx.x; item < ITEMS; item += GRID1) {
        int b = item & 15;
        int s0 = (item >> 4) * 256;
        int nrows = S1 - s0; if (nrows > 256) nrows = 256;
        const float* qkg = d_qk + b * H * D;

        float4 r[8]; float4 rq = make_float4(0.f, 0.f, 0.f, 0.f);
        // prefetch chunk 0
        #pragma unroll
        for (int i = 0; i < 8; i++) {
            int idx = t + i * 512, row = idx >> 4, c4 = idx & 15;
            if (row < nrows) {
                int s = s0 + row;
                r[i] = (s < S) ? __ldcs((const float4*)&past_key[((size_t)b * S + s) * D + c4 * 4])
                               : *(const float4*)&key[b * D + c4 * 4];
            } else r[i] = make_float4(0.f, 0.f, 0.f, 0.f);
        }
        if (t < 256) rq = *(const float4*)&qkg[hq * D + hc4 * 4];
        {
            float* qs = sm;
            float* cs = sm + 16 * CBS2;
            #pragma unroll
            for (int i = 0; i < 8; i++) {
                int idx = t + i * 512, row = idx >> 4, c4 = idx & 15;
                if (row < nrows)
                    __stcs((float4*)&ck_out[((size_t)b * S1 + s0 + row) * D + c4 * 4], r[i]);
                *(float4*)&cs[row * CBS2 + c4 * 4] = r[i];
            }
            if (t < 256) *(float4*)&qs[hq * CBS2 + hc4 * 4] = rq;
        }
        __syncthreads();

        ull acc[2][4];
        #pragma unroll
        for (int k = 0; k < 2; k++)
            #pragma unroll
            for (int m = 0; m < 4; m++) acc[k][m] = 0ull;

        for (int c = 0; c < 16; c++) {
            if (c < 15) {
                #pragma unroll
                for (int i = 0; i < 8; i++) {
                    int idx = t + i * 512, row = idx >> 4, c4 = idx & 15;
                    if (row < nrows) {
                        int s = s0 + row;
                        r[i] = (s < S) ? __ldcs((const float4*)&past_key[((size_t)b * S + s) * D + (c + 1) * 64 + c4 * 4])
                                       : *(const float4*)&key[b * D + (c + 1) * 64 + c4 * 4];
                    } else r[i] = make_float4(0.f, 0.f, 0.f, 0.f);
                }
                if (t < 256) rq = *(const float4*)&qkg[hq * D + (c + 1) * 64 + hc4 * 4];
            }
            // compute chunk c: warp tile 16 rows x 16 heads
            {
                const float* qs = sm + (c & 1) * BUF1;
                const float* cs = qs + 16 * CBS2;
                #pragma unroll 2
                for (int jp = 0; jp < 32; jp++) {
                    ull c2[2], q2[4];
                    #pragma unroll
                    for (int k = 0; k < 2; k++)
                        c2[k] = *(const ull*)&cs[(w * 16 + k * 8 + lr) * CBS2 + jp * 2];
                    #pragma unroll
                    for (int m = 0; m < 4; m++)
                        q2[m] = *(const ull*)&qs[(m * 4 + lc) * CBS2 + jp * 2];
                    #pragma unroll
                    for (int k = 0; k < 2; k++)
                        #pragma unroll
                        for (int m = 0; m < 4; m++) fma2(acc[k][m], c2[k], q2[m]);
                }
            }
            if (c < 15) {
                float* qs = sm + ((c + 1) & 1) * BUF1;
                float* cs = qs + 16 * CBS2;
                #pragma unroll
                for (int i = 0; i < 8; i++) {
                    int idx = t + i * 512, row = idx >> 4, c4 = idx & 15;
                    if (row < nrows)
                        __stcs((float4*)&ck_out[((size_t)b * S1 + s0 + row) * D + (c + 1) * 64 + c4 * 4], r[i]);
                    *(float4*)&cs[row * CBS2 + c4 * 4] = r[i];
                }
                if (t < 256) *(float4*)&qs[hq * CBS2 + hc4 * 4] = rq;
            }
            __syncthreads();
        }
        // store raw scores
        #pragma unroll
        for (int k = 0; k < 2; k++) {
            int rr = w * 16 + k * 8 + lr;
            if (rr < nrows) {
                int s = s0 + rr;
                #pragma unroll
                for (int m = 0; m < 4; m++)
                    d_scores[(b * H + m * 4 + lc) * SST + s] = sum2(acc[k][m]);
            }
        }
    }
}

// ---------------- 4. pass2: V-copy + fused softmax + ctx (512 thr) ----------------
#define VST 520
#define BUF2V (32 * VST)
#define ATT_F (16 * 33 * 2)
#define BUF2 (BUF2V + ATT_F)

__global__ __launch_bounds__(512, 1)
void pass2_kernel(const float* __restrict__ past_value,
                  const float* __restrict__ value,
                  float* __restrict__ cv_out) {
    extern __shared__ float sm[];
    float* Msm = sm + 2 * BUF2;
    float* ISsm = Msm + 16;
    int t = threadIdx.x;
    int w = t >> 5, l = t & 31;
    int lh = l >> 3, lj = l & 7;
    int jbase = w * 32;                  // 16 warps x 32 cols = 512-col half

    for (int item = blockIdx.x; item < ITEMS; item += GRID1) {
        int b = item & 15;
        int s0 = (item >> 4) * 256;
        int nrows = S1 - s0; if (nrows > 256) nrows = 256;

        // softmax stats: warp w handles head w
        {
            const float* sc = d_scores + (b * H + w) * SST;
            float mx = -1e30f;
            for (int i = l; i < S1; i += 32) mx = fmaxf(mx, sc[i]);
            mx = warp_max(mx);
            float sum = 0.f;
            for (int i = l; i < S1; i += 32) sum += __expf(sc[i] - mx);
            sum = warp_red(sum);
            if (l == 0) { Msm[w] = mx; ISsm[w] = 1.0f / sum; }
        }
        __syncthreads();
        const float* scb = d_scores + b * H * SST;
        int ah = t >> 5, ass = t & 31;   // attn staging role: 1 value/thread

        float4 r[8]; float ra;
        // prefetch chunk 0 (jh=0, scn=0)
        #pragma unroll
        for (int i = 0; i < 8; i++) {
            int idx = t + i * 512, row = idx >> 7, c4 = idx & 127;
            if (row < nrows) {
                int s = s0 + row;
                r[i] = (s < S) ? __ldcs((const float4*)&past_value[((size_t)b * S + s) * D + c4 * 4])
                               : *(const float4*)&value[b * D + c4 * 4];
            } else r[i] = make_float4(0.f, 0.f, 0.f, 0.f);
        }
        ra = (ass < nrows) ? __expf(scb[ah * SST + s0 + ass] - Msm[ah]) * ISsm[ah] : 0.f;
        {
            float* vs = sm;
            ull* as = (ull*)(sm + BUF2V);
            #pragma unroll
            for (int i = 0; i < 8; i++) {
                int idx = t + i * 512, row = idx >> 7, c4 = idx & 127;
                if (row < nrows)
                    __stcs((float4*)&cv_out[((size_t)b * S1 + s0 + row) * D + c4 * 4], r[i]);
                *(float4*)&vs[row * VST + c4 * 4] = r[i];
            }
            as[ah * 33 + ass] = dup2(ra);
        }
        __syncthreads();

        ull acc[4][2];
        #pragma unroll
        for (int a = 0; a < 4; a++)
            #pragma unroll
            for (int m = 0; m < 2; m++) acc[a][m] = 0ull;

        for (int c = 0; c < 16; c++) {
            int jh1 = (c + 1) >> 3, scn1 = (c + 1) & 7;
            if (c < 15) {
                #pragma unroll
                for (int i = 0; i < 8; i++) {
                    int idx = t + i * 512, row = idx >> 7, c4 = idx & 127;
                    int rr = scn1 * 32 + row;
                    if (rr < nrows) {
                        int s = s0 + rr;
                        r[i] = (s < S) ? __ldcs((const float4*)&past_value[((size_t)b * S + s) * D + jh1 * 512 + c4 * 4])
                                       : *(const float4*)&value[b * D + jh1 * 512 + c4 * 4];
                    } else r[i] = make_float4(0.f, 0.f, 0.f, 0.f);
                }
                int rr = scn1 * 32 + ass;
                ra = (rr < nrows) ? __expf(scb[ah * SST + s0 + rr] - Msm[ah]) * ISsm[ah] : 0.f;
            }
            // compute chunk c: warp tile 16 heads x 32 cols
            {
                const float* vs = sm + (c & 1) * BUF2;
                const ull* as = (const ull*)(vs + BUF2V);
                #pragma unroll 2
                for (int s = 0; s < 32; s++) {
                    ull a2[4], v2[2];
                    #pragma unroll
                    for (int hh = 0; hh < 4; hh++) a2[hh] = as[(lh * 4 + hh) * 33 + s];
                    #pragma unroll
                    for (int m = 0; m < 2; m++)
                        v2[m] = *(const ull*)&vs[s * VST + jbase + (lj + 8 * m) * 2];
                    #pragma unroll
                    for (int hh = 0; hh < 4; hh++)
                        #pragma unroll
                        for (int m = 0; m < 2; m++) fma2(acc[hh][m], a2[hh], v2[m]);
                }
            }
            if (c == 7 || c == 15) {
                int jh = c >> 3;
                float* cr = d_ctxraw + b * H * D;
                #pragma unroll
                for (int hh = 0; hh < 4; hh++) {
                    int h = lh * 4 + hh;
                    #pragma unroll
                    for (int m = 0; m < 2; m++) {
                        int j = jh * 512 + jbase + (lj + 8 * m) * 2;
                        atomicAdd(&cr[h * D + j],
                                  __uint_as_float((unsigned)(acc[hh][m] & 0xffffffffull)));
                        atomicAdd(&cr[h * D + j + 1],
                                  __uint_as_float((unsigned)(acc[hh][m] >> 32)));
                        acc[hh][m] = 0ull;
                    }
                }
            }
            if (c < 15) {
                float* vs = sm + ((c + 1) & 1) * BUF2;
                ull* as = (ull*)(vs + BUF2V);
                #pragma unroll
                for (int i = 0; i < 8; i++) {
                    int idx = t + i * 512, row = idx >> 7, c4 = idx & 127;
                    int rr = scn1 * 32 + row;
                    if (rr < nrows)
                        __stcs((float4*)&cv_out[((size_t)b * S1 + s0 + rr) * D + jh1 * 512 + c4 * 4], r[i]);
                    *(float4*)&vs[row * VST + c4 * 4] = r[i];
                }
                as[ah * 33 + ass] = dup2(ra);
            }
            __syncthreads();
        }
    }
}

// ---------------- 5. ctxproj = ctxraw . Wv + bv ----------------
__global__ void ctxproj_kernel(const float* __restrict__ w_in,
                               const float* __restrict__ b_in) {
    __shared__ float cs[D];
    int bh = blockIdx.x, b = bh >> 4, h = bh & 15, t = threadIdx.x;
    #pragma unroll
    for (int i = 0; i < 4; i++) cs[t + i * 256] = d_ctxraw[bh * D + t + i * 256];
    __syncthreads();
    int w = t >> 5, l = t & 31;
    #pragma unroll 1
    for (int it = 0; it < 8; it++) {
        int row = h * 64 + it * 8 + w;
        const float* wr = w_in + (size_t)(2 * D + row) * D;
        float acc = 0.f;
        #pragma unroll
        for (int p = 0; p < 8; p++) {
            float4 wv = *(const float4*)&wr[l * 4 + p * 128];
            float4 cv = *(const float4*)&cs[l * 4 + p * 128];
            acc += wv.x * cv.x + wv.y * cv.y + wv.z * cv.z + wv.w * cv.w;
        }
        acc = warp_red(acc);
        if (l == 0) d_ctxproj[b * D + row] = acc + b_in[2 * D + row];
    }
}

// ---------------- 6. out = ctxproj . Wout^T + bout ----------------
__global__ void out_kernel(const float* __restrict__ w_out,
                           const float* __restrict__ b_out,
                           float* __restrict__ out) {
    __shared__ float cp[D];
    int eg = blockIdx.x, b = blockIdx.y, t = threadIdx.x;
    #pragma unroll
    for (int i = 0; i < 4; i++) cp[t + i * 256] = d_ctxproj[b * D + t + i * 256];
    __syncthreads();
    int w = t >> 5, l = t & 31;
    #pragma unroll 1
    for (int it = 0; it < 16; it++) {
        int e = eg * 128 + it * 8 + w;
        const float* wr = w_out + (size_t)e * D;
        float acc = 0.f;
        #pragma unroll
        for (int p = 0; p < 8; p++) {
            float4 wv = *(const float4*)&wr[l * 4 + p * 128];
            float4 cv = *(const float4*)&cp[l * 4 + p * 128];
            acc += wv.x * cv.x + wv.y * cv.y + wv.z * cv.z + wv.w * cv.w;
        }
        acc = warp_red(acc);
        if (l == 0) out[b * D + e] = acc + b_out[e];
    }
}

// ---------------- launch ----------------
extern "C" void kernel_launch(void* const* d_in, const int* in_sizes, int n_in,
                              void* d_out, int out_size) {
    const float* query      = (const float*)d_in[0];
    const float* key        = (const float*)d_in[1];
    const float* value      = (const float*)d_in[2];
    const float* past_key   = (const float*)d_in[3];
    const float* past_value = (const float*)d_in[4];
    const float* w_in       = (const float*)d_in[5];
    const float* b_in       = (const float*)d_in[6];
    const float* w_out      = (const float*)d_in[7];
    const float* b_out      = (const float*)d_in[8];

    float* out = (float*)d_out;
    float* ck  = out + (size_t)B * D;
    float* cv  = ck + (size_t)B * S1 * D;

    int smem1 = 2 * BUF1 * sizeof(float);           // 147,968 B
    int smem2 = (2 * BUF2 + 32) * sizeof(float);    // 141,696 B
    cudaFuncSetAttribute(pass1_kernel, cudaFuncAttributeMaxDynamicSharedMemorySize, smem1);
    cudaFuncSetAttribute(pass2_kernel, cudaFuncAttributeMaxDynamicSharedMemorySize, smem2);

    qproj_kernel<<<B, 256>>>(query, w_in, b_in);
    qk_kernel<<<B * H, 256>>>(w_in);
    pass1_kernel<<<GRID1, 512, smem1>>>(past_key, key, ck);
    pass2_kernel<<<GRID1, 512, smem2>>>(past_value, value, cv);
    ctxproj_kernel<<<B * H, 256>>>(w_in, b_in);
    out_kernel<<<dim3(8, B), 256>>>(w_out, b_out, out);
}